// round 14
// baseline (speedup 1.0000x reference)
#include <cuda_runtime.h>
#include <cuda_fp16.h>
#include <cstdint>
#include <cstddef>

// Shape fixed by setup_inputs: B=64, S=2048, D=512, fp32.
// Outputs flattened: d_prime [64*512], probs [64*2048], logit [64*2048].
#define B_ 64
#define S_ 2048
#define D_ 512
#define CCLIP 10.0f
#define OUT_DP 0
#define OUT_PROBS (B_ * D_)
#define OUT_LOGIT (B_ * D_ + B_ * S_)

// ---- static device scratch (no allocations allowed) ----
__device__ float g_q[B_ * D_];            // q = tgt @ W_q^T
__device__ float g_u[B_ * S_];            // u logits pre-clip
__device__ float g_dppart[32 * B_ * D_];  // d' partials (32 s-chunks)
// W_ref hi/lo fp16, 32 slices in consumption order j = n*8 + ks64.
// Slice = 128 d-rows x 64 k, row = 128B, SW128-swizzled. 16KB each.
__device__ __align__(16) unsigned char g_wh[32 * 16384];
__device__ __align__(16) unsigned char g_wl[32 * 16384];

__device__ __forceinline__ uint32_t smem_u32(const void* p) {
    uint32_t a;
    asm("{ .reg .u64 t; cvta.to.shared.u64 t, %1; cvt.u32.u64 %0, t; }"
        : "=r"(a) : "l"(p));
    return a;
}
__device__ __forceinline__ uint32_t swz(uint32_t o) { return o ^ ((o >> 3) & 0x70); }

__device__ __forceinline__ void ldsm4(uint32_t* r, uint32_t addr) {
    asm volatile("ldmatrix.sync.aligned.m8n8.x4.shared.b16 {%0,%1,%2,%3}, [%4];"
        : "=r"(r[0]), "=r"(r[1]), "=r"(r[2]), "=r"(r[3]) : "r"(addr));
}
__device__ __forceinline__ void mma16816(float* c, const uint32_t* a,
                                         const uint32_t* b) {
    asm volatile(
        "mma.sync.aligned.m16n8k16.row.col.f32.f16.f16.f32 "
        "{%0,%1,%2,%3}, {%4,%5,%6,%7}, {%8,%9}, {%0,%1,%2,%3};"
        : "+f"(c[0]), "+f"(c[1]), "+f"(c[2]), "+f"(c[3])
        : "r"(a[0]), "r"(a[1]), "r"(a[2]), "r"(a[3]), "r"(b[0]), "r"(b[1]));
}
__device__ __forceinline__ void cp16(uint32_t saddr, const void* g) {
    asm volatile("cp.async.cg.shared.global [%0], [%1], 16;"
        :: "r"(saddr), "l"(g));
}
#define CP_COMMIT() asm volatile("cp.async.commit_group;" ::: "memory")
#define CP_WAIT2()  asm volatile("cp.async.wait_group 2;" ::: "memory")

__device__ __forceinline__ float fast_tanh(float x) {
    float e = __expf(2.0f * x);
    return 1.0f - __fdividef(2.0f, e + 1.0f);
}

// ===================================================================
// Kernel A: q[b,d] = sum_k tgt[b,k] * W_q[d,k]  (tiny)
// ===================================================================
__global__ void qproj_kernel(const float* __restrict__ tgt,
                             const float* __restrict__ Wq) {
    __shared__ float wrow[D_];
    const int d = blockIdx.x;
    for (int i = threadIdx.x; i < D_; i += blockDim.x) wrow[i] = Wq[d * D_ + i];
    __syncthreads();
    const int warp = threadIdx.x >> 5, lane = threadIdx.x & 31;
    for (int b = warp; b < B_; b += 8) {
        const float* t = tgt + b * D_;
        float p = 0.f;
        #pragma unroll 4
        for (int k = lane; k < D_; k += 32) p += t[k] * wrow[k];
        #pragma unroll
        for (int o = 16; o; o >>= 1) p += __shfl_xor_sync(0xffffffffu, p, o);
        if (lane == 0) g_q[b * D_ + d] = p;
    }
}

// ===================================================================
// Kernel W: split W_ref into hi/lo fp16 slices, pre-swizzled.
// w = wh + wl with wh = fp16(w): wl ~ 2^-11 |w| -> 22-bit effective.
// ===================================================================
__global__ void wsplit_kernel(const float* __restrict__ Wref) {
    const int i = blockIdx.x * blockDim.x + threadIdx.x;  // 0 .. 262143
    const float w = Wref[i];
    const int d = i >> 9, k = i & 511;
    const int n = d >> 7, r = d & 127;
    const int ks = k >> 6, c = k & 63;
    const size_t off = (size_t)(n * 8 + ks) * 16384 + swz((uint32_t)(r * 128 + c * 2));
    const __half hi = __float2half_rn(w);
    *(__half*)(g_wh + off) = hi;
    *(__half*)(g_wl + off) = __float2half_rn(w - __half2float(hi));
}

// ===================================================================
// Kernel B: fp16 2-term mma.sync GEMM + fused tanh/v-reduction.
// CTA = (b, 64-row s-tile). A (64x512 fp16) resident, converted once.
// B streamed in 32 hi/lo slices via 4-stage cp.async ring (prefetch
// depth 3) -> ONE __syncthreads per slice.
// 8 warps = 2(warp_m) x 4(warp_n), warp tile m32 x n32.
// NEW: fragment register double-buffer across ks-steps — LDSMs for
// ks+1 are issued before the MMAs of ks, so fragment latency is
// hidden behind ~256 cyc of MMA execution per step.
// ===================================================================
#define SM_A   0
#define SM_B   65536
#define SM_SQ  196608
#define SM_SV  198656
#define SM_U   200704
#define SM_TOTAL 201728

__device__ __forceinline__ void prefetchB(uint32_t sb, int j, int tid) {
    const uint32_t dst = sb + SM_B + (uint32_t)(j & 3) * 32768 + tid * 16;
    const unsigned char* sh = g_wh + (size_t)j * 16384 + tid * 16;
    const unsigned char* sl = g_wl + (size_t)j * 16384 + tid * 16;
    #pragma unroll
    for (int q = 0; q < 4; ++q) {
        cp16(dst + q * 4096, sh + q * 4096);
        cp16(dst + 16384 + q * 4096, sl + q * 4096);
    }
}

// Load all fragments for k-step `kss` into buffer `bb`.
#define LOADF(kss, bb)                                                        \
    do {                                                                      \
        ldsm4(af[bb][0], aB + swz(laneA + (kss) * 32));                       \
        ldsm4(af[bb][1], aB + swz(laneA + 2048 + (kss) * 32));                \
        _Pragma("unroll")                                                     \
        for (int _p = 0; _p < 2; ++_p) {                                      \
            const uint32_t _bo =                                              \
                swz(laneB + (uint32_t)_p * 2048 + (kss) * 32);                \
            ldsm4(bh[bb][_p], bH + _bo);                                      \
            ldsm4(bl[bb][_p], bL + _bo);                                      \
        }                                                                     \
    } while (0)

__global__ __launch_bounds__(256)
void fused_mma_kernel(const float* __restrict__ src,
                      const float* __restrict__ v) {
    extern __shared__ char smem[];
    const uint32_t sb = smem_u32(smem);
    const int tid = threadIdx.x, wid = tid >> 5, lane = tid & 31;
    const int warp_m = wid & 1, warp_n = wid >> 1;   // 2 x 4
    const int sz = blockIdx.x, b = blockIdx.y;

    float* sq = (float*)(smem + SM_SQ);
    float* sv = (float*)(smem + SM_SV);
    float* u_sm = (float*)(smem + SM_U);             // [4][64]
    for (int i = tid; i < D_; i += 256) {
        sq[i] = g_q[b * D_ + i];
        sv[i] = v[i];
    }
    if (tid < 256) u_sm[tid] = 0.f;

    // kick off B slices 0,1,2
    prefetchB(sb, 0, tid); CP_COMMIT();
    prefetchB(sb, 1, tid); CP_COMMIT();
    prefetchB(sb, 2, tid); CP_COMMIT();

    // ---- convert A (64 rows x K=512) fp32 -> fp16, once ----
    const float* srcB = src + ((size_t)(b * S_ + sz * 64)) * D_;
    #pragma unroll 4
    for (int it = 0; it < 32; ++it) {
        const int idx = tid + it * 256;          // 0..8191 float4s
        const int r = idx >> 7, f4 = idx & 127;
        const int k0 = f4 * 4, sl = k0 >> 6, c = k0 & 63;
        float4 x = *(const float4*)(srcB + (size_t)r * D_ + k0);
        const uint32_t ob = (uint32_t)sl * 8192 + swz((uint32_t)(r * 128 + c * 2));
        *(__half2*)(smem + SM_A + ob) = __floats2half2_rn(x.x, x.y);
        *(__half2*)(smem + SM_A + ob + 4) = __floats2half2_rn(x.z, x.w);
    }

    // lane-invariant fragment byte offsets (pre-swizzle)
    const uint32_t laneA = (uint32_t)(warp_m * 4096 + (lane & 15) * 128 +
                                      ((lane >> 4) << 4));
    const uint32_t laneB = (uint32_t)(warp_n * 4096 +
                                      ((lane & 7) + ((lane >> 4) & 1) * 8) * 128 +
                                      (((lane >> 3) & 1) << 4));

    float acc[2][4][4];                          // [mt][frag n8][e]
    float* accf = &acc[0][0][0];
    #pragma unroll
    for (int t = 0; t < 32; ++t) accf[t] = 0.f;

    uint32_t af[2][2][4];                        // [buf][mt]
    uint32_t bh[2][2][4], bl[2][2][4];           // [buf][ntp]

    for (int i = 0; i < 32; ++i) {
        const int n = i >> 3, sl = i & 7;
        CP_WAIT2();        // slice i landed (groups i+1, i+2 may be pending)
        __syncthreads();   // visible CTA-wide; slot (i+3)&3 reads done (iter i-1)

        if (i < 29) prefetchB(sb, i + 3, tid);
        CP_COMMIT();       // unconditional: keeps group arithmetic uniform

        const uint32_t aB = sb + SM_A + (uint32_t)sl * 8192;
        const uint32_t bH = sb + SM_B + (uint32_t)(i & 3) * 32768;
        const uint32_t bL = bH + 16384;

        LOADF(0, 0);       // prime the fragment pipeline for this slice
        #pragma unroll
        for (int ks = 0; ks < 4; ++ks) {
            const int cur = ks & 1;
            if (ks < 3) LOADF(ks + 1, cur ^ 1);   // hide behind ks's MMAs
            // 8 independent hi-MMAs on distinct accumulators
            #pragma unroll
            for (int mt = 0; mt < 2; ++mt)
                #pragma unroll
                for (int ntp = 0; ntp < 2; ++ntp) {
                    mma16816(acc[mt][2 * ntp], af[cur][mt], bh[cur][ntp]);
                    mma16816(acc[mt][2 * ntp + 1], af[cur][mt], bh[cur][ntp] + 2);
                }
            // lo terms: dependent reuse is 8 MMA issues later
            #pragma unroll
            for (int mt = 0; mt < 2; ++mt)
                #pragma unroll
                for (int ntp = 0; ntp < 2; ++ntp) {
                    mma16816(acc[mt][2 * ntp], af[cur][mt], bl[cur][ntp]);
                    mma16816(acc[mt][2 * ntp + 1], af[cur][mt], bl[cur][ntp] + 2);
                }
        }

        if (sl == 7) {
            // ---- epilogue for d-chunk n (warp covers 32 d-cols) ----
            const int g = lane >> 2;
            #pragma unroll
            for (int mt = 0; mt < 2; ++mt) {
                float s0 = 0.f, s1 = 0.f;
                #pragma unroll
                for (int f = 0; f < 4; ++f) {
                    const int d = n * 128 + warp_n * 32 + f * 8 + (lane & 3) * 2;
                    const float* c = acc[mt][f];
                    s0 += sv[d] * fast_tanh(sq[d] + c[0])
                        + sv[d + 1] * fast_tanh(sq[d + 1] + c[1]);
                    s1 += sv[d] * fast_tanh(sq[d] + c[2])
                        + sv[d + 1] * fast_tanh(sq[d + 1] + c[3]);
                }
                s0 += __shfl_xor_sync(0xffffffffu, s0, 1);
                s0 += __shfl_xor_sync(0xffffffffu, s0, 2);
                s1 += __shfl_xor_sync(0xffffffffu, s1, 1);
                s1 += __shfl_xor_sync(0xffffffffu, s1, 2);
                if ((lane & 3) == 0) {
                    const int r0 = warp_m * 32 + mt * 16 + g;
                    u_sm[warp_n * 64 + r0] += s0;
                    u_sm[warp_n * 64 + r0 + 8] += s1;
                }
            }
            #pragma unroll
            for (int t = 0; t < 32; ++t) accf[t] = 0.f;
        }
    }

    __syncthreads();
    if (tid < 64)
        g_u[b * S_ + sz * 64 + tid] =
            (u_sm[tid] + u_sm[tid + 64]) + (u_sm[tid + 128] + u_sm[tid + 192]);
}

// ===================================================================
// Kernel C: logit = C*tanh(u); softmax over S (shift by constant C).
// ===================================================================
__global__ void softmax_kernel(float* __restrict__ out) {
    const int b = blockIdx.x, tid = threadIdx.x;
    float* logit = out + OUT_LOGIT + b * S_;
    float* probs = out + OUT_PROBS + b * S_;
    __shared__ float red[256];

    float lsum = 0.f;
    for (int s = tid; s < S_; s += 256) {
        const float l = CCLIP * fast_tanh(g_u[b * S_ + s]);
        logit[s] = l;
        lsum += expf(l - CCLIP);
    }
    red[tid] = lsum;
    __syncthreads();
    for (int o = 128; o; o >>= 1) {
        if (tid < o) red[tid] += red[tid + o];
        __syncthreads();
    }
    const float inv = 1.f / red[0];
    for (int s = tid; s < S_; s += 256)
        probs[s] = expf(logit[s] - CCLIP) * inv;
}

// ===================================================================
// Kernel D: d' partials; 32 s-chunks of 64 rows, float4, deterministic.
// ===================================================================
__global__ void dprime_kernel(const float* __restrict__ src,
                              const float* __restrict__ out) {
    const float* probs = out + OUT_PROBS;
    const int sc = blockIdx.x, b = blockIdx.y, t = threadIdx.x;  // t: 0..127
    __shared__ float p_sm[64];
    if (t < 64) p_sm[t] = probs[b * S_ + sc * 64 + t];
    __syncthreads();
    const float4* sp = (const float4*)(src + ((size_t)(b * S_ + sc * 64)) * D_) + t;
    float4 acc = make_float4(0.f, 0.f, 0.f, 0.f);
    #pragma unroll 8
    for (int s = 0; s < 64; ++s) {
        float4 x = sp[(size_t)s * 128];
        const float p = p_sm[s];
        acc.x += p * x.x; acc.y += p * x.y;
        acc.z += p * x.z; acc.w += p * x.w;
    }
    *(float4*)(g_dppart + ((size_t)sc * B_ + b) * D_ + t * 4) = acc;
}

__global__ void dpsum_kernel(float* __restrict__ out) {
    const int b = blockIdx.x, d = threadIdx.x;
    float acc = 0.f;
    #pragma unroll
    for (int sc = 0; sc < 32; ++sc)
        acc += g_dppart[((size_t)sc * B_ + b) * D_ + d];
    out[OUT_DP + b * D_ + d] = acc;
}

// ===================================================================
extern "C" void kernel_launch(void* const* d_in, const int* in_sizes, int n_in,
                              void* d_out, int out_size) {
    const float* src  = (const float*)d_in[0];  // [64, 2048, 512]
    const float* tgt  = (const float*)d_in[1];  // [64, 1, 512]
    const float* Wq   = (const float*)d_in[2];  // [512, 512]
    const float* Wref = (const float*)d_in[3];  // [512, 512]
    const float* v    = (const float*)d_in[4];  // [512]
    float* out = (float*)d_out;

    qproj_kernel<<<D_, 256>>>(tgt, Wq);
    wsplit_kernel<<<512, 512>>>(Wref);

    cudaFuncSetAttribute(fused_mma_kernel,
                         cudaFuncAttributeMaxDynamicSharedMemorySize, SM_TOTAL);
    fused_mma_kernel<<<dim3(32, B_), 256, SM_TOTAL>>>(src, v);

    softmax_kernel<<<B_, 256>>>(out);

    dprime_kernel<<<dim3(32, B_), 128>>>(src, out);
    dpsum_kernel<<<B_, D_>>>(out);
}

// round 16
// speedup vs baseline: 1.2034x; 1.2034x over previous
#include <cuda_runtime.h>
#include <cuda_fp16.h>
#include <cstdint>
#include <cstddef>

// Shape fixed by setup_inputs: B=64, S=2048, D=512, fp32.
// Outputs flattened: d_prime [64*512], probs [64*2048], logit [64*2048].
#define B_ 64
#define S_ 2048
#define D_ 512
#define CCLIP 10.0f
#define OUT_DP 0
#define OUT_PROBS (B_ * D_)
#define OUT_LOGIT (B_ * D_ + B_ * S_)

// ---- static device scratch (no allocations allowed) ----
__device__ float g_q[B_ * D_];            // q = tgt @ W_q^T
__device__ float g_u[B_ * S_];            // u logits pre-clip
__device__ float g_dppart[32 * B_ * D_];  // d' partials (32 s-chunks)
// W_ref hi/lo fp16, 32 slices in consumption order j = n*8 + ks64.
// Slice = 128 d-rows x 64 k, row = 128B, SW128-swizzled. 16KB each.
__device__ __align__(16) unsigned char g_wh[32 * 16384];
__device__ __align__(16) unsigned char g_wl[32 * 16384];

__device__ __forceinline__ uint32_t smem_u32(const void* p) {
    uint32_t a;
    asm("{ .reg .u64 t; cvta.to.shared.u64 t, %1; cvt.u32.u64 %0, t; }"
        : "=r"(a) : "l"(p));
    return a;
}
__device__ __forceinline__ uint32_t swz(uint32_t o) { return o ^ ((o >> 3) & 0x70); }

__device__ __forceinline__ void ldsm4(uint32_t* r, uint32_t addr) {
    asm volatile("ldmatrix.sync.aligned.m8n8.x4.shared.b16 {%0,%1,%2,%3}, [%4];"
        : "=r"(r[0]), "=r"(r[1]), "=r"(r[2]), "=r"(r[3]) : "r"(addr));
}
__device__ __forceinline__ void mma16816(float* c, const uint32_t* a,
                                         const uint32_t* b) {
    asm volatile(
        "mma.sync.aligned.m16n8k16.row.col.f32.f16.f16.f32 "
        "{%0,%1,%2,%3}, {%4,%5,%6,%7}, {%8,%9}, {%0,%1,%2,%3};"
        : "+f"(c[0]), "+f"(c[1]), "+f"(c[2]), "+f"(c[3])
        : "r"(a[0]), "r"(a[1]), "r"(a[2]), "r"(a[3]), "r"(b[0]), "r"(b[1]));
}
__device__ __forceinline__ void cp16(uint32_t saddr, const void* g) {
    asm volatile("cp.async.cg.shared.global [%0], [%1], 16;"
        :: "r"(saddr), "l"(g));
}
#define CP_COMMIT() asm volatile("cp.async.commit_group;" ::: "memory")
#define CP_WAIT0()  asm volatile("cp.async.wait_group 0;" ::: "memory")

__device__ __forceinline__ float fast_tanh(float x) {
    float e = __expf(2.0f * x);
    return 1.0f - __fdividef(2.0f, e + 1.0f);
}

// ===================================================================
// Kernel A: q[b,d] = sum_k tgt[b,k] * W_q[d,k]  (tiny)
// ===================================================================
__global__ void qproj_kernel(const float* __restrict__ tgt,
                             const float* __restrict__ Wq) {
    __shared__ float wrow[D_];
    const int d = blockIdx.x;
    for (int i = threadIdx.x; i < D_; i += blockDim.x) wrow[i] = Wq[d * D_ + i];
    __syncthreads();
    const int warp = threadIdx.x >> 5, lane = threadIdx.x & 31;
    for (int b = warp; b < B_; b += 8) {
        const float* t = tgt + b * D_;
        float p = 0.f;
        #pragma unroll 4
        for (int k = lane; k < D_; k += 32) p += t[k] * wrow[k];
        #pragma unroll
        for (int o = 16; o; o >>= 1) p += __shfl_xor_sync(0xffffffffu, p, o);
        if (lane == 0) g_q[b * D_ + d] = p;
    }
}

// ===================================================================
// Kernel W: split W_ref into hi/lo fp16 slices, pre-swizzled.
// w = wh + wl with wh = fp16(w): wl ~ 2^-11 |w| -> 22-bit effective.
// ===================================================================
__global__ void wsplit_kernel(const float* __restrict__ Wref) {
    const int i = blockIdx.x * blockDim.x + threadIdx.x;  // 0 .. 262143
    const float w = Wref[i];
    const int d = i >> 9, k = i & 511;
    const int n = d >> 7, r = d & 127;
    const int ks = k >> 6, c = k & 63;
    const size_t off = (size_t)(n * 8 + ks) * 16384 + swz((uint32_t)(r * 128 + c * 2));
    const __half hi = __float2half_rn(w);
    *(__half*)(g_wh + off) = hi;
    *(__half*)(g_wl + off) = __float2half_rn(w - __half2float(hi));
}

// ===================================================================
// Kernel B: fp16 2-term mma.sync GEMM + fused tanh/v-reduction.
// CTA = (b, 128-row s-tile), 512 threads (4 warps/SMSP for latency
// hiding). A (128x512 fp16, 128KB) resident, converted once. B
// streamed in 32 hi/lo slices via 2-stage cp.async ring, depth-1
// prefetch (load of slice i+1 overlaps ~2000-cyc compute of slice i).
// 16 warps = 4(warp_m: 32 s-rows) x 4(warp_n: 32 d-cols).
// Per ks: 8 independent hi-MMAs then 8 lo-MMAs (RAW 8 issues apart).
// Halves CTA count, sync count, and W L2 traffic vs 64-row tiles.
// ===================================================================
#define SM_A   0
#define SM_B   131072
#define SM_SQ  196608
#define SM_SV  198656
#define SM_U   200704
#define SM_TOTAL 202752

__device__ __forceinline__ void prefetchB(uint32_t sb, int j, int tid) {
    const uint32_t dst = sb + SM_B + (uint32_t)(j & 1) * 32768 + tid * 16;
    const unsigned char* sh = g_wh + (size_t)j * 16384 + tid * 16;
    const unsigned char* sl = g_wl + (size_t)j * 16384 + tid * 16;
    #pragma unroll
    for (int q = 0; q < 2; ++q) {
        cp16(dst + q * 8192, sh + q * 8192);
        cp16(dst + 16384 + q * 8192, sl + q * 8192);
    }
}

__global__ __launch_bounds__(512)
void fused_mma_kernel(const float* __restrict__ src,
                      const float* __restrict__ v) {
    extern __shared__ char smem[];
    const uint32_t sb = smem_u32(smem);
    const int tid = threadIdx.x, wid = tid >> 5, lane = tid & 31;
    const int warp_m = wid & 3, warp_n = wid >> 2;   // 4 x 4
    const int sz = blockIdx.x, b = blockIdx.y;

    float* sq = (float*)(smem + SM_SQ);
    float* sv = (float*)(smem + SM_SV);
    float* u_sm = (float*)(smem + SM_U);             // [4 warp_n][128]
    for (int i = tid; i < D_; i += 512) {
        sq[i] = g_q[b * D_ + i];
        sv[i] = v[i];
    }
    u_sm[tid] = 0.f;

    // kick off B slices 0,1
    prefetchB(sb, 0, tid); CP_COMMIT();
    prefetchB(sb, 1, tid); CP_COMMIT();

    // ---- convert A (128 rows x K=512) fp32 -> fp16, once ----
    const float* srcB = src + ((size_t)(b * S_ + sz * 128)) * D_;
    #pragma unroll 4
    for (int it = 0; it < 32; ++it) {
        const int idx = tid + it * 512;          // 0..16383 float4s
        const int r = idx >> 7, f4 = idx & 127;
        const int k0 = f4 * 4, sl = k0 >> 6, c = k0 & 63;
        float4 x = *(const float4*)(srcB + (size_t)r * D_ + k0);
        const uint32_t ob = (uint32_t)sl * 16384 + swz((uint32_t)(r * 128 + c * 2));
        *(__half2*)(smem + SM_A + ob) = __floats2half2_rn(x.x, x.y);
        *(__half2*)(smem + SM_A + ob + 4) = __floats2half2_rn(x.z, x.w);
    }

    // lane-invariant fragment byte offsets (pre-swizzle)
    // A rows: warp_m*32 + mt*16 + (lane&15); k-byte: (lane>>4)*16 + ks*32
    const uint32_t laneA = (uint32_t)(warp_m * 4096 + (lane & 15) * 128 +
                                      ((lane >> 4) << 4));
    // B rows: warp_n*32 + ntp*16 + (lane&7)+((lane>>4)&1)*8; k-byte: ((lane>>3)&1)*16
    const uint32_t laneB = (uint32_t)(warp_n * 4096 +
                                      ((lane & 7) + ((lane >> 4) & 1) * 8) * 128 +
                                      (((lane >> 3) & 1) << 4));

    float acc[2][4][4];                          // [mt][frag n8][e]
    float* accf = &acc[0][0][0];
    #pragma unroll
    for (int t = 0; t < 32; ++t) accf[t] = 0.f;

    for (int i = 0; i < 32; ++i) {
        const int n = i >> 3, sl = i & 7;
        CP_WAIT0();        // slice i landed (last committed group)
        __syncthreads();   // visible CTA-wide; slot (i+1)&1 reads done (iter i-1)

        if (i < 31) prefetchB(sb, i + 1, tid);
        CP_COMMIT();       // unconditional: keeps group arithmetic uniform

        const uint32_t aB = sb + SM_A + (uint32_t)sl * 16384;
        const uint32_t bH = sb + SM_B + (uint32_t)(i & 1) * 32768;
        const uint32_t bL = bH + 16384;

        #pragma unroll
        for (int ks = 0; ks < 4; ++ks) {
            uint32_t af[2][4];
            ldsm4(af[0], aB + swz(laneA + ks * 32));
            ldsm4(af[1], aB + swz(laneA + 2048 + ks * 32));
            uint32_t bh[2][4], bl[2][4];
            #pragma unroll
            for (int ntp = 0; ntp < 2; ++ntp) {
                const uint32_t bo = swz(laneB + (uint32_t)ntp * 2048 + ks * 32);
                ldsm4(bh[ntp], bH + bo);
                ldsm4(bl[ntp], bL + bo);
            }
            // 8 independent hi-MMAs on distinct accumulators
            #pragma unroll
            for (int mt = 0; mt < 2; ++mt)
                #pragma unroll
                for (int ntp = 0; ntp < 2; ++ntp) {
                    mma16816(acc[mt][2 * ntp], af[mt], bh[ntp]);
                    mma16816(acc[mt][2 * ntp + 1], af[mt], bh[ntp] + 2);
                }
            // lo terms: dependent reuse is 8 MMA issues later
            #pragma unroll
            for (int mt = 0; mt < 2; ++mt)
                #pragma unroll
                for (int ntp = 0; ntp < 2; ++ntp) {
                    mma16816(acc[mt][2 * ntp], af[mt], bl[ntp]);
                    mma16816(acc[mt][2 * ntp + 1], af[mt], bl[ntp] + 2);
                }
        }

        if (sl == 7) {
            // ---- epilogue for d-chunk n (warp covers 32 d-cols) ----
            const int g = lane >> 2;
            #pragma unroll
            for (int mt = 0; mt < 2; ++mt) {
                float s0 = 0.f, s1 = 0.f;
                #pragma unroll
                for (int f = 0; f < 4; ++f) {
                    const int d = n * 128 + warp_n * 32 + f * 8 + (lane & 3) * 2;
                    const float* c = acc[mt][f];
                    s0 += sv[d] * fast_tanh(sq[d] + c[0])
                        + sv[d + 1] * fast_tanh(sq[d + 1] + c[1]);
                    s1 += sv[d] * fast_tanh(sq[d] + c[2])
                        + sv[d + 1] * fast_tanh(sq[d + 1] + c[3]);
                }
                s0 += __shfl_xor_sync(0xffffffffu, s0, 1);
                s0 += __shfl_xor_sync(0xffffffffu, s0, 2);
                s1 += __shfl_xor_sync(0xffffffffu, s1, 1);
                s1 += __shfl_xor_sync(0xffffffffu, s1, 2);
                if ((lane & 3) == 0) {
                    const int r0 = warp_m * 32 + mt * 16 + g;
                    u_sm[warp_n * 128 + r0] += s0;
                    u_sm[warp_n * 128 + r0 + 8] += s1;
                }
            }
            #pragma unroll
            for (int t = 0; t < 32; ++t) accf[t] = 0.f;
        }
    }

    __syncthreads();
    if (tid < 128)
        g_u[b * S_ + sz * 128 + tid] =
            (u_sm[tid] + u_sm[tid + 128]) + (u_sm[tid + 256] + u_sm[tid + 384]);
}

// ===================================================================
// Kernel C: logit = C*tanh(u); softmax over S (shift by constant C).
// ===================================================================
__global__ void softmax_kernel(float* __restrict__ out) {
    const int b = blockIdx.x, tid = threadIdx.x;
    float* logit = out + OUT_LOGIT + b * S_;
    float* probs = out + OUT_PROBS + b * S_;
    __shared__ float red[256];

    float lsum = 0.f;
    for (int s = tid; s < S_; s += 256) {
        const float l = CCLIP * fast_tanh(g_u[b * S_ + s]);
        logit[s] = l;
        lsum += expf(l - CCLIP);
    }
    red[tid] = lsum;
    __syncthreads();
    for (int o = 128; o; o >>= 1) {
        if (tid < o) red[tid] += red[tid + o];
        __syncthreads();
    }
    const float inv = 1.f / red[0];
    for (int s = tid; s < S_; s += 256)
        probs[s] = expf(logit[s] - CCLIP) * inv;
}

// ===================================================================
// Kernel D: d' partials; 32 s-chunks of 64 rows, float4, deterministic.
// ===================================================================
__global__ void dprime_kernel(const float* __restrict__ src,
                              const float* __restrict__ out) {
    const float* probs = out + OUT_PROBS;
    const int sc = blockIdx.x, b = blockIdx.y, t = threadIdx.x;  // t: 0..127
    __shared__ float p_sm[64];
    if (t < 64) p_sm[t] = probs[b * S_ + sc * 64 + t];
    __syncthreads();
    const float4* sp = (const float4*)(src + ((size_t)(b * S_ + sc * 64)) * D_) + t;
    float4 acc = make_float4(0.f, 0.f, 0.f, 0.f);
    #pragma unroll 8
    for (int s = 0; s < 64; ++s) {
        float4 x = sp[(size_t)s * 128];
        const float p = p_sm[s];
        acc.x += p * x.x; acc.y += p * x.y;
        acc.z += p * x.z; acc.w += p * x.w;
    }
    *(float4*)(g_dppart + ((size_t)sc * B_ + b) * D_ + t * 4) = acc;
}

__global__ void dpsum_kernel(float* __restrict__ out) {
    const int b = blockIdx.x, d = threadIdx.x;
    float acc = 0.f;
    #pragma unroll
    for (int sc = 0; sc < 32; ++sc)
        acc += g_dppart[((size_t)sc * B_ + b) * D_ + d];
    out[OUT_DP + b * D_ + d] = acc;
}

// ===================================================================
extern "C" void kernel_launch(void* const* d_in, const int* in_sizes, int n_in,
                              void* d_out, int out_size) {
    const float* src  = (const float*)d_in[0];  // [64, 2048, 512]
    const float* tgt  = (const float*)d_in[1];  // [64, 1, 512]
    const float* Wq   = (const float*)d_in[2];  // [512, 512]
    const float* Wref = (const float*)d_in[3];  // [512, 512]
    const float* v    = (const float*)d_in[4];  // [512]
    float* out = (float*)d_out;

    qproj_kernel<<<D_, 256>>>(tgt, Wq);
    wsplit_kernel<<<512, 512>>>(Wref);

    cudaFuncSetAttribute(fused_mma_kernel,
                         cudaFuncAttributeMaxDynamicSharedMemorySize, SM_TOTAL);
    fused_mma_kernel<<<dim3(16, B_), 512, SM_TOTAL>>>(src, v);

    softmax_kernel<<<B_, 256>>>(out);

    dprime_kernel<<<dim3(32, B_), 128>>>(src, out);
    dpsum_kernel<<<B_, D_>>>(out);
}